// round 9
// baseline (speedup 1.0000x reference)
#include <cuda_runtime.h>

// Problem constants (fixed shapes per setup_inputs)
#define N_PTS   65536
#define DLAT    64
#define KC      64
#define DDATA   512
#define ALPHA_F 0.001f
#define EPS_F   1e-8f
#define N_TILES (N_PTS / 64)
#define RS      68          // enc_s row stride (floats); 68*4=272 is 16B-aligned

// Scratch (device globals; no allocation allowed)
__device__ float g_C[KC * DLAT];
__device__ float g_Cnum[KC * DLAT];
__device__ float g_Cden[KC];
__device__ float g_loss;
__device__ float g_dec;

// ---------------------------------------------------------------------------
// Packed fp32x2 helpers (Blackwell FFMA2: 2 FMAs per fma-pipe issue slot)
// ---------------------------------------------------------------------------
__device__ __forceinline__ void fma2(unsigned long long& d, unsigned long long a,
                                     unsigned long long b) {
    asm("fma.rn.f32x2 %0, %1, %2, %0;" : "+l"(d) : "l"(a), "l"(b));
}
__device__ __forceinline__ unsigned long long dup2(float x) {
    unsigned long long r;
    asm("mov.b64 %0, {%1, %1};" : "=l"(r) : "f"(x));
    return r;
}
__device__ __forceinline__ float2 unpk(unsigned long long v) {
    float2 f;
    asm("mov.b64 {%0, %1}, %2;" : "=f"(f.x), "=f"(f.y) : "l"(v));
    return f;
}

// ---------------------------------------------------------------------------
// Zero all accumulators (C itself is initialized by async D2D copy of enc[:64])
// ---------------------------------------------------------------------------
__global__ void init_kernel() {
    int i = blockIdx.x * blockDim.x + threadIdx.x;
    if (i < KC * DLAT) g_Cnum[i] = 0.f;
    if (i < KC)        g_Cden[i] = 0.f;
    if (i == 0) { g_loss = 0.f; g_dec = 0.f; }
}

// ---------------------------------------------------------------------------
// Decoder loss: sum((X - Dc)^2), float4 grid-stride, block-reduced atomicAdd
// ---------------------------------------------------------------------------
__global__ __launch_bounds__(256) void dec_kernel(const float4* __restrict__ X,
                                                  const float4* __restrict__ Dc,
                                                  int n4) {
    float acc = 0.f;
    int stride = gridDim.x * blockDim.x;
    for (int i = blockIdx.x * blockDim.x + threadIdx.x; i < n4; i += stride) {
        float4 a = X[i], b = Dc[i];
        float d0 = a.x - b.x, d1 = a.y - b.y, d2 = a.z - b.z, d3 = a.w - b.w;
        acc += d0 * d0 + d1 * d1 + d2 * d2 + d3 * d3;
    }
    __shared__ float red[8];
    #pragma unroll
    for (int o = 16; o; o >>= 1) acc += __shfl_xor_sync(0xffffffffu, acc, o);
    int w = threadIdx.x >> 5;
    if ((threadIdx.x & 31) == 0) red[w] = acc;
    __syncthreads();
    if (threadIdx.x < 32) {
        float v = (threadIdx.x < 8) ? red[threadIdx.x] : 0.f;
        #pragma unroll
        for (int o = 4; o; o >>= 1) v += __shfl_xor_sync(0xffffffffu, v, o);
        if (threadIdx.x == 0) atomicAdd(&g_dec, v);
    }
}

// ---------------------------------------------------------------------------
// Fused k-means iteration:
//   d2 = |x|^2 + |c|^2 - 2 x.c  (clamped >= 0), r = softmax(-d2),
//   Cnum += r^T enc, Cden += sum_p r   (skipped on last iter)
//   loss += sum_p sum_k r*d2           (only on last iter)
// Thread layout: 256 threads = (tx 0..15 -> 4 k's) x (ty 0..15 -> 4 p's / 4 d's)
// Both GEMM phases run on packed fp32x2 FMAs (k-pairs in A, d-pairs in B).
// ---------------------------------------------------------------------------
__global__ __launch_bounds__(256) void assign_kernel(const float* __restrict__ enc,
                                                     int last) {
    extern __shared__ float smem[];
    float* enc_s = smem;               // 64 x RS   : enc tile [p][d]
    float* ct_s  = enc_s + 64 * RS;    // 64 x 64   : C transposed [d][k]
    float* r_s   = ct_s + 4096;        // 64 x 64   : r [p][k]
    float* x2_s  = r_s + 4096;         // 64
    float* c2_s  = x2_s + 64;          // 64
    float* red_s = c2_s + 64;          // 8

    int tid = threadIdx.x;
    int tx = tid & 15, ty = tid >> 4;
    int pb = ty * 4;                   // p-base (phase A) == d-base (phase B)
    int kb = tx * 4;                   // k-base

    // Stage C transposed (conflict-free shared stores: consecutive k per i)
    for (int i = tid; i < KC * DLAT; i += 256) {
        int k = i & 63, d = i >> 6;
        ct_s[d * 64 + k] = g_C[k * 64 + d];
    }
    __syncthreads();
    if (tid < KC) {
        float s = 0.f;
        #pragma unroll 8
        for (int d = 0; d < DLAT; d++) { float v = ct_s[d * 64 + tid]; s += v * v; }
        c2_s[tid] = s;
    }
    __syncthreads();

    unsigned long long cn2[4][2] = {};   // cn[k][d-pair] packed accumulators
    float den[4] = {};
    float lacc = 0.f;

    for (int tile = blockIdx.x; tile < N_TILES; tile += gridDim.x) {
        // ---- load enc tile (coalesced float4) ----
        const float4* eg = (const float4*)(enc + (size_t)tile * 4096);
        #pragma unroll
        for (int i = 0; i < 4; i++) {
            int lin = tid + i * 256;           // 1024 float4s
            int row = lin >> 4, c4 = lin & 15;
            *(float4*)&enc_s[row * RS + c4 * 4] = eg[lin];
        }
        __syncthreads();
        if (tid < 64) {
            float s = 0.f;
            const float* xr = &enc_s[tid * RS];
            #pragma unroll 8
            for (int d = 0; d < DLAT; d++) s += xr[d] * xr[d];
            x2_s[tid] = s;
        }
        __syncthreads();

        // ---- phase A: 4p x 4k dot products over D=64 (fp32x2, k-pairs) ----
        unsigned long long acc2[4][2] = {};   // acc[p][{k0,k1}],[{k2,k3}]
        #pragma unroll 4
        for (int d4 = 0; d4 < DLAT; d4 += 4) {
            float4 xv0 = *(const float4*)&enc_s[(pb + 0) * RS + d4];
            float4 xv1 = *(const float4*)&enc_s[(pb + 1) * RS + d4];
            float4 xv2 = *(const float4*)&enc_s[(pb + 2) * RS + d4];
            float4 xv3 = *(const float4*)&enc_s[(pb + 3) * RS + d4];
            #pragma unroll
            for (int dd = 0; dd < 4; dd++) {
                ulonglong2 cv = *(const ulonglong2*)&ct_s[(d4 + dd) * 64 + kb];
                unsigned long long a0 = dup2(((const float*)&xv0)[dd]);
                unsigned long long a1 = dup2(((const float*)&xv1)[dd]);
                unsigned long long a2 = dup2(((const float*)&xv2)[dd]);
                unsigned long long a3 = dup2(((const float*)&xv3)[dd]);
                fma2(acc2[0][0], a0, cv.x); fma2(acc2[0][1], a0, cv.y);
                fma2(acc2[1][0], a1, cv.x); fma2(acc2[1][1], a1, cv.y);
                fma2(acc2[2][0], a2, cv.x); fma2(acc2[2][1], a2, cv.y);
                fma2(acc2[3][0], a3, cv.x); fma2(acc2[3][1], a3, cv.y);
            }
        }

        // ---- softmax over k (16 tx-lanes x 4 regs); loss on last iter ----
        #pragma unroll
        for (int pp = 0; pp < 4; pp++) {
            float x2p = x2_s[pb + pp];
            float2 a01 = unpk(acc2[pp][0]);
            float2 a23 = unpk(acc2[pp][1]);
            float av[4] = {a01.x, a01.y, a23.x, a23.y};
            float d2v[4];
            float mn = 3.402823e38f;
            #pragma unroll
            for (int kk = 0; kk < 4; kk++) {
                float v = fmaxf(fmaf(-2.f, av[kk], x2p + c2_s[kb + kk]), 0.f);
                d2v[kk] = v;
                mn = fminf(mn, v);
            }
            #pragma unroll
            for (int o = 8; o; o >>= 1) mn = fminf(mn, __shfl_xor_sync(0xffffffffu, mn, o));
            float e0 = __expf(mn - d2v[0]);
            float e1 = __expf(mn - d2v[1]);
            float e2 = __expf(mn - d2v[2]);
            float e3 = __expf(mn - d2v[3]);
            float s = e0 + e1 + e2 + e3;
            #pragma unroll
            for (int o = 8; o; o >>= 1) s += __shfl_xor_sync(0xffffffffu, s, o);
            float inv = 1.f / s;
            if (last) {
                float l = (e0 * d2v[0] + e1 * d2v[1] + e2 * d2v[2] + e3 * d2v[3]) * inv;
                #pragma unroll
                for (int o = 8; o; o >>= 1) l += __shfl_xor_sync(0xffffffffu, l, o);
                if (tx == 0) lacc += l;
            } else {
                *(float4*)&r_s[(pb + pp) * 64 + kb] =
                    make_float4(e0 * inv, e1 * inv, e2 * inv, e3 * inv);
            }
        }

        // ---- phase B: rank-64 update (fp32x2, d-pairs), 4k x 4d regs ----
        if (!last) {
            __syncthreads();
            #pragma unroll 4
            for (int p = 0; p < 64; p++) {
                float4 rv = *(const float4*)&r_s[p * 64 + kb];
                ulonglong2 ev = *(const ulonglong2*)&enc_s[p * RS + pb];
                unsigned long long r0 = dup2(rv.x);
                unsigned long long r1 = dup2(rv.y);
                unsigned long long r2 = dup2(rv.z);
                unsigned long long r3 = dup2(rv.w);
                fma2(cn2[0][0], r0, ev.x); fma2(cn2[0][1], r0, ev.y);
                fma2(cn2[1][0], r1, ev.x); fma2(cn2[1][1], r1, ev.y);
                fma2(cn2[2][0], r2, ev.x); fma2(cn2[2][1], r2, ev.y);
                fma2(cn2[3][0], r3, ev.x); fma2(cn2[3][1], r3, ev.y);
                if (ty == 0) { den[0] += rv.x; den[1] += rv.y; den[2] += rv.z; den[3] += rv.w; }
            }
        }
        __syncthreads();  // before next tile overwrites enc_s / r_s
    }

    // ---- block epilogue ----
    if (!last) {
        #pragma unroll
        for (int kk = 0; kk < 4; kk++) {
            float2 c01 = unpk(cn2[kk][0]);
            float2 c23 = unpk(cn2[kk][1]);
            atomicAdd(&g_Cnum[(kb + kk) * 64 + pb + 0], c01.x);
            atomicAdd(&g_Cnum[(kb + kk) * 64 + pb + 1], c01.y);
            atomicAdd(&g_Cnum[(kb + kk) * 64 + pb + 2], c23.x);
            atomicAdd(&g_Cnum[(kb + kk) * 64 + pb + 3], c23.y);
        }
        if (ty == 0) {
            #pragma unroll
            for (int kk = 0; kk < 4; kk++) atomicAdd(&g_Cden[kb + kk], den[kk]);
        }
    } else {
        #pragma unroll
        for (int o = 16; o; o >>= 1) lacc += __shfl_xor_sync(0xffffffffu, lacc, o);
        int w = tid >> 5;
        if ((tid & 31) == 0) red_s[w] = lacc;
        __syncthreads();
        if (tid < 32) {
            float v = (tid < 8) ? red_s[tid] : 0.f;
            #pragma unroll
            for (int o = 4; o; o >>= 1) v += __shfl_xor_sync(0xffffffffu, v, o);
            if (tid == 0) atomicAdd(&g_loss, v);
        }
    }
}

// ---------------------------------------------------------------------------
// C = Cnum / (Cden + eps); re-zero accumulators. 64 blocks (one per k),
// 64 threads (one per d) — latency-parallel instead of one serial block.
// ---------------------------------------------------------------------------
__global__ void finalize_kernel() {
    __shared__ float dsh;
    int k = blockIdx.x, d = threadIdx.x;
    if (d == 0) { dsh = g_Cden[k] + EPS_F; g_Cden[k] = 0.f; }
    __syncthreads();
    int i = k * 64 + d;
    g_C[i] = g_Cnum[i] / dsh;
    g_Cnum[i] = 0.f;
}

__global__ void combine_kernel(float* out) {
    out[0] = g_dec * (1.f / (float)(N_PTS * (long long)DDATA))
           + ALPHA_F * g_loss * (1.f / (float)N_PTS);
}

// ---------------------------------------------------------------------------
#define SMEM_BYTES ((64 * RS + 4096 + 4096 + 64 + 64 + 8) * (int)sizeof(float))

extern "C" void kernel_launch(void* const* d_in, const int* in_sizes, int n_in,
                              void* d_out, int out_size) {
    const float* X   = (const float*)d_in[0];
    const float* enc = (const float*)d_in[1];
    const float* dcd = (const float*)d_in[2];
    float* out = (float*)d_out;

    // >48KB dynamic smem opt-in (host attribute set; idempotent, capture-safe)
    cudaFuncSetAttribute(assign_kernel,
                         cudaFuncAttributeMaxDynamicSharedMemorySize, SMEM_BYTES);

    // C init = enc[:K] (first 64 rows are contiguous)
    cudaMemcpyToSymbolAsync(g_C, enc, KC * DLAT * sizeof(float), 0,
                            cudaMemcpyDeviceToDevice, 0);
    init_kernel<<<17, 256>>>();
    dec_kernel<<<1184, 256>>>((const float4*)X, (const float4*)dcd,
                              (N_PTS * DDATA) / 4);
    for (int it = 0; it < 10; it++) {
        assign_kernel<<<148, 256, SMEM_BYTES>>>(enc, (it == 9) ? 1 : 0);
        if (it < 9) finalize_kernel<<<64, 64>>>();
    }
    combine_kernel<<<1, 1>>>(out);
}

// round 12
// speedup vs baseline: 1.3953x; 1.3953x over previous
#include <cuda_runtime.h>
#include <cstdint>

// Problem constants (fixed shapes per setup_inputs)
#define N_PTS   65536
#define DLAT    64
#define KC      64
#define DDATA   512
#define ALPHA_F 0.001f
#define EPS_F   1e-8f
#define TILE_P  128
#define NT      (N_PTS / TILE_P)     // 512 tiles of 128 points

// SMEM layout (floats). Strides chosen so every fragment-load lane pattern is
// a bijection onto the 32 banks:
//   eA stride 68: A-frag addr%32 = 4g+q  (bijective)
//   eB/ct stride 72: B-frag addr%32 = 8q+g (bijective)
//   rT stride 132: A-frag addr%32 = 4g+q (bijective)
#define STRA 68
#define STRB 72
#define STRR 132
#define OFF_EA 0
#define OFF_EB (OFF_EA + 128 * STRA)       // 8704
#define OFF_CT (OFF_EB + 128 * STRB)       // 17920
#define OFF_RT (OFF_CT + 64 * STRB)        // 22528
#define OFF_C2 (OFF_RT + 64 * STRR)        // 30976
#define OFF_X2 (OFF_C2 + 64)               // 31040
#define OFF_RED (OFF_X2 + 128)             // 31168
#define SMEM_FLOATS (OFF_RED + 8)          // 31176
#define DSMEM_BYTES (SMEM_FLOATS * 4)      // 124704

// Scratch (device globals; no allocation allowed). Triple-buffered accumulators:
// iter j reads (j-1)%3, writes j%3, zeroes (j+1)%3 (idle buffer) — all disjoint.
__device__ float g_C[KC * DLAT];
__device__ float g_num[3][KC * DLAT];
__device__ float g_den[3][KC];
__device__ float g_loss;
__device__ float g_dec;

// ---------------------------------------------------------------------------
// Helpers
// ---------------------------------------------------------------------------
__device__ __forceinline__ float tf32f(float f) {
    uint32_t r; asm("cvt.rna.tf32.f32 %0, %1;" : "=r"(r) : "f"(f));
    return __uint_as_float(r);
}
__device__ __forceinline__ void mma8(float* c, uint32_t a0, uint32_t a1,
                                     uint32_t a2, uint32_t a3,
                                     uint32_t b0, uint32_t b1) {
    asm volatile(
        "mma.sync.aligned.m16n8k8.row.col.f32.tf32.tf32.f32 "
        "{%0,%1,%2,%3}, {%4,%5,%6,%7}, {%8,%9}, {%0,%1,%2,%3};"
        : "+f"(c[0]), "+f"(c[1]), "+f"(c[2]), "+f"(c[3])
        : "r"(a0), "r"(a1), "r"(a2), "r"(a3), "r"(b0), "r"(b1));
}

// ---------------------------------------------------------------------------
// Zero accumulators (3 buffers) + scalars
// ---------------------------------------------------------------------------
__global__ void init_kernel() {
    int i = blockIdx.x * blockDim.x + threadIdx.x;
    if (i < 3 * KC * DLAT) ((float*)g_num)[i] = 0.f;
    if (i < 3 * KC)        ((float*)g_den)[i] = 0.f;
    if (i == 0) { g_loss = 0.f; g_dec = 0.f; }
}

// ---------------------------------------------------------------------------
// Decoder loss: sum((X - Dc)^2), float4 grid-stride, block-reduced atomicAdd
// ---------------------------------------------------------------------------
__global__ __launch_bounds__(256) void dec_kernel(const float4* __restrict__ X,
                                                  const float4* __restrict__ Dc,
                                                  int n4) {
    float acc = 0.f;
    int stride = gridDim.x * blockDim.x;
    for (int i = blockIdx.x * blockDim.x + threadIdx.x; i < n4; i += stride) {
        float4 a = X[i], b = Dc[i];
        float d0 = a.x - b.x, d1 = a.y - b.y, d2 = a.z - b.z, d3 = a.w - b.w;
        acc += d0 * d0 + d1 * d1 + d2 * d2 + d3 * d3;
    }
    __shared__ float red[8];
    #pragma unroll
    for (int o = 16; o; o >>= 1) acc += __shfl_xor_sync(0xffffffffu, acc, o);
    int w = threadIdx.x >> 5;
    if ((threadIdx.x & 31) == 0) red[w] = acc;
    __syncthreads();
    if (threadIdx.x < 32) {
        float v = (threadIdx.x < 8) ? red[threadIdx.x] : 0.f;
        #pragma unroll
        for (int o = 4; o; o >>= 1) v += __shfl_xor_sync(0xffffffffu, v, o);
        if (threadIdx.x == 0) atomicAdd(&g_dec, v);
    }
}

// ---------------------------------------------------------------------------
// Fused k-means iteration on tf32 mma.sync (m16n8k8, Ampere-path HMMA):
//   phase A: dot[p][k] = enc_tile @ C^T   (8 warps x 64 MMAs)
//   softmax over k (quad-lane reduction; x2 cancels in logits)
//   phase B: Cnum += r^T enc (persistent register accumulators across tiles)
//   last iter: loss += sum r * max(x2 + c2 - 2 dot, 0)
// ---------------------------------------------------------------------------
__global__ __launch_bounds__(256, 1) void assign_kernel(const float* __restrict__ enc,
                                                        int it) {
    extern __shared__ float sm[];
    float* eA  = sm + OFF_EA;
    float* eB  = sm + OFF_EB;
    float* ct  = sm + OFF_CT;
    float* rT  = sm + OFF_RT;
    float* c2s = sm + OFF_C2;
    float* x2s = sm + OFF_X2;
    float* red = sm + OFF_RED;

    int tid = threadIdx.x, lane = tid & 31, w = tid >> 5;
    int g = lane >> 2, q = lane & 3;
    int last = (it == 9);

    // ---- stage C (fp32) into scratch (rT area), then ct (tf32) + c2 ----
    float* csrc = rT;
    if (it == 0) {
        for (int i = tid; i < KC * DLAT; i += 256) csrc[i] = g_C[i];
    } else {
        const float* nr = g_num[(it - 1) % 3];
        const float* dr = g_den[(it - 1) % 3];
        for (int i = tid; i < KC * DLAT; i += 256) csrc[i] = nr[i] / (dr[i >> 6] + EPS_F);
    }
    __syncthreads();
    for (int i = tid; i < KC * DLAT; i += 256) {
        int k = i & 63, d = i >> 6;
        ct[d * STRB + k] = tf32f(csrc[i]);     // ct[d][k] = C[k][d]
    }
    if (tid < KC) {
        float s = 0.f;
        #pragma unroll 8
        for (int d = 0; d < DLAT; d++) { float v = csrc[tid * 64 + d]; s += v * v; }
        c2s[tid] = s;
    }
    // zero the buffer iter it+1 will write (idle this iter; launch-serialized)
    if (it <= 7) {
        int gt = blockIdx.x * 256 + tid;
        int nb3 = (it + 1) % 3;
        if (gt < KC * DLAT) g_num[nb3][gt] = 0.f;
        if (gt < KC)        g_den[nb3][gt] = 0.f;
    }
    __syncthreads();   // csrc (rT) reads done before tiles overwrite rT

    float cn[4][4] = {};     // phase-B accumulators, persist across tiles
    float den_acc = 0.f;
    float lacc = 0.f;
    int mw = w * 16;                 // phase A: warp's 16-row point stripe
    int mb = w >> 1;                 // phase B: k-block (4 blocks x 2 warps)
    int nbase = (w & 1) * 4;         // phase B: 4 of 8 d-blocks per warp

    for (int tile = blockIdx.x; tile < NT; tile += gridDim.x) {
        // ---- stage enc tile: tf32, two copies (stride 68 + stride 72) ----
        const float4* eg = (const float4*)(enc + (size_t)tile * (TILE_P * DLAT));
        #pragma unroll
        for (int i = 0; i < 8; i++) {
            int lin = tid + i * 256;           // 2048 float4
            int row = lin >> 4, c0 = (lin & 15) * 4;
            float4 v = eg[lin];
            float4 t = make_float4(tf32f(v.x), tf32f(v.y), tf32f(v.z), tf32f(v.w));
            *(float4*)&eA[row * STRA + c0] = t;
            *(float4*)&eB[row * STRB + c0] = t;
        }
        __syncthreads();
        if (last) {
            if (tid < TILE_P) {
                float s = 0.f;
                #pragma unroll
                for (int d = 0; d < DLAT; d += 4) {
                    float4 v = *(const float4*)&eA[tid * STRA + d];
                    s += v.x * v.x + v.y * v.y + v.z * v.z + v.w * v.w;
                }
                x2s[tid] = s;
            }
            __syncthreads();
        }

        // ---- phase A: dot[p][k], 8 kblocks x 8 nblocks of m16n8k8 ----
        float acc[8][4];
        #pragma unroll
        for (int nb = 0; nb < 8; nb++) { acc[nb][0]=0.f; acc[nb][1]=0.f; acc[nb][2]=0.f; acc[nb][3]=0.f; }
        #pragma unroll
        for (int kb8 = 0; kb8 < 8; kb8++) {
            int kb = kb8 * 8;
            uint32_t a0 = __float_as_uint(eA[(mw + g) * STRA + kb + q]);
            uint32_t a1 = __float_as_uint(eA[(mw + g + 8) * STRA + kb + q]);
            uint32_t a2 = __float_as_uint(eA[(mw + g) * STRA + kb + q + 4]);
            uint32_t a3 = __float_as_uint(eA[(mw + g + 8) * STRA + kb + q + 4]);
            #pragma unroll
            for (int nb = 0; nb < 8; nb++) {
                uint32_t b0 = __float_as_uint(ct[(kb + q) * STRB + nb * 8 + g]);
                uint32_t b1 = __float_as_uint(ct[(kb + q + 4) * STRB + nb * 8 + g]);
                mma8(acc[nb], a0, a1, a2, a3, b0, b1);
            }
        }

        // ---- softmax over k per row; rows (mw+g) and (mw+g+8) ----
        #pragma unroll
        for (int rr = 0; rr < 2; rr++) {
            int p = mw + g + rr * 8;
            float sv[16];
            float mx = -3.402823e38f;
            #pragma unroll
            for (int nb = 0; nb < 8; nb++)
                #pragma unroll
                for (int e = 0; e < 2; e++) {
                    float s = fmaf(2.f, acc[nb][rr * 2 + e], -c2s[nb * 8 + 2 * q + e]);
                    sv[nb * 2 + e] = s;
                    mx = fmaxf(mx, s);
                }
            mx = fmaxf(mx, __shfl_xor_sync(0xffffffffu, mx, 1));
            mx = fmaxf(mx, __shfl_xor_sync(0xffffffffu, mx, 2));
            float sum = 0.f;
            float ev[16];
            #pragma unroll
            for (int j = 0; j < 16; j++) { ev[j] = __expf(sv[j] - mx); sum += ev[j]; }
            sum += __shfl_xor_sync(0xffffffffu, sum, 1);
            sum += __shfl_xor_sync(0xffffffffu, sum, 2);
            if (!last) {
                float iv = 1.f / sum;
                #pragma unroll
                for (int nb = 0; nb < 8; nb++)
                    #pragma unroll
                    for (int e = 0; e < 2; e++)
                        rT[(nb * 8 + 2 * q + e) * STRR + p] = tf32f(ev[nb * 2 + e] * iv);
            } else {
                float x2p = x2s[p];
                float l = 0.f;
                #pragma unroll
                for (int j = 0; j < 16; j++)
                    l += ev[j] * fmaxf(x2p - sv[j], 0.f);   // d2 = x2 + c2 - 2dot
                lacc += l / sum;
            }
        }

        if (!last) {
            __syncthreads();   // rT complete
            // ---- Cden partials: thread owns k = tid>>2, quarter q of p ----
            {
                const float4* rp = (const float4*)&rT[(tid >> 2) * STRR + (tid & 3) * 32];
                float ds = 0.f;
                #pragma unroll
                for (int j = 0; j < 8; j++) { float4 v = rp[j]; ds += v.x + v.y + v.z + v.w; }
                den_acc += ds;
            }
            // ---- phase B: Cnum[k][d] += r^T enc, 16 pblocks x 4 nblocks ----
            #pragma unroll
            for (int ib = 0; ib < 16; ib++) {
                int pb = ib * 8;
                uint32_t a0 = __float_as_uint(rT[(mb * 16 + g) * STRR + pb + q]);
                uint32_t a1 = __float_as_uint(rT[(mb * 16 + g + 8) * STRR + pb + q]);
                uint32_t a2 = __float_as_uint(rT[(mb * 16 + g) * STRR + pb + q + 4]);
                uint32_t a3 = __float_as_uint(rT[(mb * 16 + g + 8) * STRR + pb + q + 4]);
                #pragma unroll
                for (int nb4 = 0; nb4 < 4; nb4++) {
                    int nb = nbase + nb4;
                    uint32_t b0 = __float_as_uint(eB[(pb + q) * STRB + nb * 8 + g]);
                    uint32_t b1 = __float_as_uint(eB[(pb + q + 4) * STRB + nb * 8 + g]);
                    mma8(cn[nb4], a0, a1, a2, a3, b0, b1);
                }
            }
        }
        __syncthreads();   // protect eA/eB/rT before next tile staging
    }

    // ---- block epilogue ----
    if (!last) {
        float* nw = g_num[it % 3];
        #pragma unroll
        for (int nb4 = 0; nb4 < 4; nb4++) {
            int n0 = (nbase + nb4) * 8 + 2 * q;
            atomicAdd(&nw[(mb * 16 + g) * 64 + n0],     cn[nb4][0]);
            atomicAdd(&nw[(mb * 16 + g) * 64 + n0 + 1], cn[nb4][1]);
            atomicAdd(&nw[(mb * 16 + g + 8) * 64 + n0],     cn[nb4][2]);
            atomicAdd(&nw[(mb * 16 + g + 8) * 64 + n0 + 1], cn[nb4][3]);
        }
        den_acc += __shfl_xor_sync(0xffffffffu, den_acc, 1);
        den_acc += __shfl_xor_sync(0xffffffffu, den_acc, 2);
        if ((tid & 3) == 0) atomicAdd(&g_den[it % 3][tid >> 2], den_acc);
    } else {
        #pragma unroll
        for (int o = 16; o; o >>= 1) lacc += __shfl_xor_sync(0xffffffffu, lacc, o);
        if (lane == 0) red[w] = lacc;
        __syncthreads();
        if (tid < 32) {
            float v = (tid < 8) ? red[tid] : 0.f;
            #pragma unroll
            for (int o = 4; o; o >>= 1) v += __shfl_xor_sync(0xffffffffu, v, o);
            if (tid == 0) atomicAdd(&g_loss, v);
        }
    }
}

__global__ void combine_kernel(float* out) {
    out[0] = g_dec * (1.f / (float)(N_PTS * (long long)DDATA))
           + ALPHA_F * g_loss * (1.f / (float)N_PTS);
}

// ---------------------------------------------------------------------------
extern "C" void kernel_launch(void* const* d_in, const int* in_sizes, int n_in,
                              void* d_out, int out_size) {
    const float* X   = (const float*)d_in[0];
    const float* enc = (const float*)d_in[1];
    const float* dcd = (const float*)d_in[2];
    float* out = (float*)d_out;

    cudaFuncSetAttribute(assign_kernel,
                         cudaFuncAttributeMaxDynamicSharedMemorySize, DSMEM_BYTES);

    // C init = enc[:K] (first 64 rows contiguous)
    cudaMemcpyToSymbolAsync(g_C, enc, KC * DLAT * sizeof(float), 0,
                            cudaMemcpyDeviceToDevice, 0);
    init_kernel<<<48, 256>>>();
    dec_kernel<<<1184, 256>>>((const float4*)X, (const float4*)dcd,
                              (N_PTS * DDATA) / 4);
    for (int it = 0; it < 10; it++)
        assign_kernel<<<148, 256, DSMEM_BYTES>>>(enc, it);
    combine_kernel<<<1, 1>>>(out);
}

// round 13
// speedup vs baseline: 1.9667x; 1.4096x over previous
#include <cuda_runtime.h>
#include <cstdint>

// Problem constants (fixed shapes per setup_inputs)
#define N_PTS   65536
#define DLAT    64
#define KC      64
#define DDATA   512
#define ALPHA_F 0.001f
#define EPS_F   1e-8f
#define TILE_P  128
#define NT      (N_PTS / TILE_P)     // 512 tiles of 128 points

// SMEM layout (floats). Single enc copy at stride 72:
//   B-frags: addr%32 = 8q+g  -> bijective (conflict-free)
//   A-frags: addr%32 = 8g+q  -> 2-way conflict (g vs g+4) — accepted
//   rT stride 132: A-frag addr%32 = 4g+q -> bijective
#define STRB 72
#define STRR 132
#define OFF_ES 0
#define OFF_CT (OFF_ES + 128 * STRB)       // 9216
#define OFF_RT (OFF_CT + 64 * STRB)        // 13824
#define OFF_C2 (OFF_RT + 64 * STRR)        // 22272
#define OFF_X2 (OFF_C2 + 64)               // 22336
#define OFF_RED (OFF_X2 + 128)             // 22464
#define SMEM_FLOATS (OFF_RED + 8)          // 22472
#define DSMEM_BYTES (SMEM_FLOATS * 4)      // 89888  -> 2 CTAs/SM

// Scratch (device globals; no allocation allowed). Triple-buffered accumulators:
// iter j reads (j-1)%3, writes j%3, zeroes (j+1)%3 (idle buffer) — all disjoint.
__device__ float g_C[KC * DLAT];
__device__ float g_num[3][KC * DLAT];
__device__ float g_den[3][KC];
__device__ float g_loss;
__device__ float g_dec;

// ---------------------------------------------------------------------------
// tf32 m16n8k8 MMA (Ampere-path; operands are raw fp32 bits — HW uses the
// top 19 bits, i.e. tf32 truncation, which is within our error budget)
// ---------------------------------------------------------------------------
__device__ __forceinline__ void mma8(float* c, uint32_t a0, uint32_t a1,
                                     uint32_t a2, uint32_t a3,
                                     uint32_t b0, uint32_t b1) {
    asm volatile(
        "mma.sync.aligned.m16n8k8.row.col.f32.tf32.tf32.f32 "
        "{%0,%1,%2,%3}, {%4,%5,%6,%7}, {%8,%9}, {%0,%1,%2,%3};"
        : "+f"(c[0]), "+f"(c[1]), "+f"(c[2]), "+f"(c[3])
        : "r"(a0), "r"(a1), "r"(a2), "r"(a3), "r"(b0), "r"(b1));
}

// ---------------------------------------------------------------------------
// Zero accumulators (3 buffers) + scalars
// ---------------------------------------------------------------------------
__global__ void init_kernel() {
    int i = blockIdx.x * blockDim.x + threadIdx.x;
    if (i < 3 * KC * DLAT) ((float*)g_num)[i] = 0.f;
    if (i < 3 * KC)        ((float*)g_den)[i] = 0.f;
    if (i == 0) { g_loss = 0.f; g_dec = 0.f; }
}

// ---------------------------------------------------------------------------
// Decoder loss: sum((X - Dc)^2), float4 grid-stride, block-reduced atomicAdd
// ---------------------------------------------------------------------------
__global__ __launch_bounds__(256) void dec_kernel(const float4* __restrict__ X,
                                                  const float4* __restrict__ Dc,
                                                  int n4) {
    float acc = 0.f;
    int stride = gridDim.x * blockDim.x;
    for (int i = blockIdx.x * blockDim.x + threadIdx.x; i < n4; i += stride) {
        float4 a = X[i], b = Dc[i];
        float d0 = a.x - b.x, d1 = a.y - b.y, d2 = a.z - b.z, d3 = a.w - b.w;
        acc += d0 * d0 + d1 * d1 + d2 * d2 + d3 * d3;
    }
    __shared__ float red[8];
    #pragma unroll
    for (int o = 16; o; o >>= 1) acc += __shfl_xor_sync(0xffffffffu, acc, o);
    int w = threadIdx.x >> 5;
    if ((threadIdx.x & 31) == 0) red[w] = acc;
    __syncthreads();
    if (threadIdx.x < 32) {
        float v = (threadIdx.x < 8) ? red[threadIdx.x] : 0.f;
        #pragma unroll
        for (int o = 4; o; o >>= 1) v += __shfl_xor_sync(0xffffffffu, v, o);
        if (threadIdx.x == 0) atomicAdd(&g_dec, v);
    }
}

// ---------------------------------------------------------------------------
// Fused k-means iteration on tf32 mma.sync (m16n8k8):
//   phase A: dot[p][k] = enc_tile @ C^T   (8 warps x 64 MMAs)
//   softmax over k (quad-lane reduction; x2 cancels in logits)
//   phase B: Cnum += r^T enc (persistent register accumulators across tiles)
//   last iter: loss += sum r * max(x2 + c2 - 2 dot, 0)
// 2 CTAs/SM (grid 296, 89.9KB smem, <=128 regs) to hide sync/LDS latency.
// ---------------------------------------------------------------------------
__global__ __launch_bounds__(256, 2) void assign_kernel(const float* __restrict__ enc,
                                                        int it) {
    extern __shared__ float sm[];
    float* eS  = sm + OFF_ES;
    float* ct  = sm + OFF_CT;
    float* rT  = sm + OFF_RT;
    float* c2s = sm + OFF_C2;
    float* x2s = sm + OFF_X2;
    float* red = sm + OFF_RED;

    int tid = threadIdx.x, lane = tid & 31, w = tid >> 5;
    int g = lane >> 2, q = lane & 3;
    int last = (it == 9);

    // ---- stage C (fp32) into scratch (rT area), then ct + c2 ----
    float* csrc = rT;
    if (it == 0) {
        for (int i = tid; i < KC * DLAT; i += 256) csrc[i] = g_C[i];
    } else {
        const float* nr = g_num[(it - 1) % 3];
        const float* dr = g_den[(it - 1) % 3];
        for (int i = tid; i < KC * DLAT; i += 256) csrc[i] = nr[i] / (dr[i >> 6] + EPS_F);
    }
    __syncthreads();
    for (int i = tid; i < KC * DLAT; i += 256) {
        int k = i & 63, d = i >> 6;
        ct[d * STRB + k] = csrc[i];            // ct[d][k] = C[k][d]
    }
    if (tid < KC) {
        float s = 0.f;
        #pragma unroll 8
        for (int d = 0; d < DLAT; d++) { float v = csrc[tid * 64 + d]; s += v * v; }
        c2s[tid] = s;
    }
    // zero the buffer iter it+1 will write (idle this iter; launch-serialized)
    if (it <= 7) {
        int gt = blockIdx.x * 256 + tid;
        int nb3 = (it + 1) % 3;
        if (gt < KC * DLAT) g_num[nb3][gt] = 0.f;
        if (gt < KC)        g_den[nb3][gt] = 0.f;
    }
    __syncthreads();   // csrc (rT) reads done before tiles overwrite rT

    float cn[4][4] = {};     // phase-B accumulators, persist across tiles
    float den_acc = 0.f;
    float lacc = 0.f;
    int mw = w * 16;                 // phase A: warp's 16-row point stripe
    int mb = w >> 1;                 // phase B: k-block (4 blocks x 2 warps)
    int nbase = (w & 1) * 4;         // phase B: 4 of 8 d-blocks per warp

    for (int tile = blockIdx.x; tile < NT; tile += gridDim.x) {
        // ---- stage enc tile (single stride-72 copy, raw fp32) ----
        const float4* eg = (const float4*)(enc + (size_t)tile * (TILE_P * DLAT));
        #pragma unroll
        for (int i = 0; i < 8; i++) {
            int lin = tid + i * 256;           // 2048 float4
            int row = lin >> 4, c0 = (lin & 15) * 4;
            *(float4*)&eS[row * STRB + c0] = eg[lin];
        }
        __syncthreads();
        if (last) {
            if (tid < TILE_P) {
                float s = 0.f;
                #pragma unroll
                for (int d = 0; d < DLAT; d += 4) {
                    float4 v = *(const float4*)&eS[tid * STRB + d];
                    s += v.x * v.x + v.y * v.y + v.z * v.z + v.w * v.w;
                }
                x2s[tid] = s;
            }
            __syncthreads();
        }

        // ---- phase A: dot[p][k], 8 kblocks x 8 nblocks of m16n8k8 ----
        float acc[8][4];
        #pragma unroll
        for (int nb = 0; nb < 8; nb++) { acc[nb][0]=0.f; acc[nb][1]=0.f; acc[nb][2]=0.f; acc[nb][3]=0.f; }
        #pragma unroll
        for (int kb8 = 0; kb8 < 8; kb8++) {
            int kb = kb8 * 8;
            uint32_t a0 = __float_as_uint(eS[(mw + g) * STRB + kb + q]);
            uint32_t a1 = __float_as_uint(eS[(mw + g + 8) * STRB + kb + q]);
            uint32_t a2 = __float_as_uint(eS[(mw + g) * STRB + kb + q + 4]);
            uint32_t a3 = __float_as_uint(eS[(mw + g + 8) * STRB + kb + q + 4]);
            #pragma unroll
            for (int nb = 0; nb < 8; nb++) {
                uint32_t b0 = __float_as_uint(ct[(kb + q) * STRB + nb * 8 + g]);
                uint32_t b1 = __float_as_uint(ct[(kb + q + 4) * STRB + nb * 8 + g]);
                mma8(acc[nb], a0, a1, a2, a3, b0, b1);
            }
        }

        // ---- softmax over k per row; rows (mw+g) and (mw+g+8) ----
        #pragma unroll
        for (int rr = 0; rr < 2; rr++) {
            int p = mw + g + rr * 8;
            float sv[16];
            float mx = -3.402823e38f;
            #pragma unroll
            for (int nb = 0; nb < 8; nb++)
                #pragma unroll
                for (int e = 0; e < 2; e++) {
                    float s = fmaf(2.f, acc[nb][rr * 2 + e], -c2s[nb * 8 + 2 * q + e]);
                    sv[nb * 2 + e] = s;
                    mx = fmaxf(mx, s);
                }
            mx = fmaxf(mx, __shfl_xor_sync(0xffffffffu, mx, 1));
            mx = fmaxf(mx, __shfl_xor_sync(0xffffffffu, mx, 2));
            float sum = 0.f;
            float ev[16];
            #pragma unroll
            for (int j = 0; j < 16; j++) { ev[j] = __expf(sv[j] - mx); sum += ev[j]; }
            sum += __shfl_xor_sync(0xffffffffu, sum, 1);
            sum += __shfl_xor_sync(0xffffffffu, sum, 2);
            if (!last) {
                float iv = 1.f / sum;
                #pragma unroll
                for (int nb = 0; nb < 8; nb++)
                    #pragma unroll
                    for (int e = 0; e < 2; e++)
                        rT[(nb * 8 + 2 * q + e) * STRR + p] = ev[nb * 2 + e] * iv;
            } else {
                float x2p = x2s[p];
                float l = 0.f;
                #pragma unroll
                for (int j = 0; j < 16; j++)
                    l += ev[j] * fmaxf(x2p - sv[j], 0.f);   // d2 = x2 + c2 - 2dot
                lacc += l / sum;
            }
        }

        if (!last) {
            __syncthreads();   // rT complete
            // ---- Cden partials: thread owns k = tid>>2, quarter q of p ----
            {
                const float4* rp = (const float4*)&rT[(tid >> 2) * STRR + (tid & 3) * 32];
                float ds = 0.f;
                #pragma unroll
                for (int j = 0; j < 8; j++) { float4 v = rp[j]; ds += v.x + v.y + v.z + v.w; }
                den_acc += ds;
            }
            // ---- phase B: Cnum[k][d] += r^T enc, 16 pblocks x 4 nblocks ----
            #pragma unroll
            for (int ib = 0; ib < 16; ib++) {
                int pb = ib * 8;
                uint32_t a0 = __float_as_uint(rT[(mb * 16 + g) * STRR + pb + q]);
                uint32_t a1 = __float_as_uint(rT[(mb * 16 + g + 8) * STRR + pb + q]);
                uint32_t a2 = __float_as_uint(rT[(mb * 16 + g) * STRR + pb + q + 4]);
                uint32_t a3 = __float_as_uint(rT[(mb * 16 + g + 8) * STRR + pb + q + 4]);
                #pragma unroll
                for (int nb4 = 0; nb4 < 4; nb4++) {
                    int nb = nbase + nb4;
                    uint32_t b0 = __float_as_uint(eS[(pb + q) * STRB + nb * 8 + g]);
                    uint32_t b1 = __float_as_uint(eS[(pb + q + 4) * STRB + nb * 8 + g]);
                    mma8(cn[nb4], a0, a1, a2, a3, b0, b1);
                }
            }
        }
        __syncthreads();   // protect eS/rT before next tile staging
    }

    // ---- block epilogue ----
    if (!last) {
        float* nw = g_num[it % 3];
        #pragma unroll
        for (int nb4 = 0; nb4 < 4; nb4++) {
            int n0 = (nbase + nb4) * 8 + 2 * q;
            atomicAdd(&nw[(mb * 16 + g) * 64 + n0],     cn[nb4][0]);
            atomicAdd(&nw[(mb * 16 + g) * 64 + n0 + 1], cn[nb4][1]);
            atomicAdd(&nw[(mb * 16 + g + 8) * 64 + n0],     cn[nb4][2]);
            atomicAdd(&nw[(mb * 16 + g + 8) * 64 + n0 + 1], cn[nb4][3]);
        }
        den_acc += __shfl_xor_sync(0xffffffffu, den_acc, 1);
        den_acc += __shfl_xor_sync(0xffffffffu, den_acc, 2);
        if ((tid & 3) == 0) atomicAdd(&g_den[it % 3][tid >> 2], den_acc);
    } else {
        #pragma unroll
        for (int o = 16; o; o >>= 1) lacc += __shfl_xor_sync(0xffffffffu, lacc, o);
        if (lane == 0) red[w] = lacc;
        __syncthreads();
        if (tid < 32) {
            float v = (tid < 8) ? red[tid] : 0.f;
            #pragma unroll
            for (int o = 4; o; o >>= 1) v += __shfl_xor_sync(0xffffffffu, v, o);
            if (tid == 0) atomicAdd(&g_loss, v);
        }
    }
}

__global__ void combine_kernel(float* out) {
    out[0] = g_dec * (1.f / (float)(N_PTS * (long long)DDATA))
           + ALPHA_F * g_loss * (1.f / (float)N_PTS);
}

// ---------------------------------------------------------------------------
extern "C" void kernel_launch(void* const* d_in, const int* in_sizes, int n_in,
                              void* d_out, int out_size) {
    const float* X   = (const float*)d_in[0];
    const float* enc = (const float*)d_in[1];
    const float* dcd = (const float*)d_in[2];
    float* out = (float*)d_out;

    cudaFuncSetAttribute(assign_kernel,
                         cudaFuncAttributeMaxDynamicSharedMemorySize, DSMEM_BYTES);

    // C init = enc[:K] (first 64 rows contiguous)
    cudaMemcpyToSymbolAsync(g_C, enc, KC * DLAT * sizeof(float), 0,
                            cudaMemcpyDeviceToDevice, 0);
    init_kernel<<<48, 256>>>();
    dec_kernel<<<1184, 256>>>((const float4*)X, (const float4*)dcd,
                              (N_PTS * DDATA) / 4);
    for (int it = 0; it < 10; it++)
        assign_kernel<<<296, 256, DSMEM_BYTES>>>(enc, it);
    combine_kernel<<<1, 1>>>(out);
}